// round 17
// baseline (speedup 1.0000x reference)
#include <cuda_runtime.h>
#include <cstdint>

// ---------------------------------------------------------------------------
// FocalLoss (RetinaNet) — persistent fused kernel, fine-grained tile queue.
// B=8, A=65536, C=80, M=32.
// Tile = 128 anchors of one image (4096 tiles). A block pulls tiles from an
// atomic queue (with one-ahead prefetch hiding the ATOMG latency under
// phase A), runs per tile:
//   Phase A: division-free IoU argmax (iou_m > iou_b <=> inter_m*S_b >
//            inter_b*S_m, S=area_a+area_m; thresholds 3*inter>=S (0.5),
//            3.5*inter>=S (0.4)); smooth-L1 reg loss; positive count;
//            per-positive classification fix-up.
//   Phase B: ALPHA=0.5 => only the negative focal formula:
//            clssum += w * v^2 * max(lg2(1-v), lg2(1e-4)), w in {0,-0.5ln2}.
//            SINGLE front-loaded batch of 8 ld.global.cs.v2.u64 (=LDG.128)
//            per thread (2560 float4 / 320 thr = 8), packed f32x2 math
//            (R8-validated neg4_acc).
// Small tiles kill the R16 quantization tail (t_tile 15-20us -> ~3.5us).
// Last block (ticket) finalizes out[2] and resets scratch for graph replay.
// ---------------------------------------------------------------------------

#define MAX_B   8
#define MAX_M   64
#define ABLK    128
#define NTHR    320
#define NWARP   (NTHR / 32)
#define NBLK    444          /* 3 blocks/SM x 148 SMs, single resident wave */

__device__ double g_cls_sum[MAX_B];
__device__ double g_reg_sum[MAX_B];
__device__ int    g_pos_cnt[MAX_B];
__device__ int    g_done;
__device__ int    g_tile_ctr;

__device__ __forceinline__ float lg2f(float x) {
    float r;
    asm("lg2.approx.f32 %0, %1;" : "=f"(r) : "f"(x));
    return r;
}

typedef unsigned long long ull;

__device__ __forceinline__ ull pack2(float lo, float hi) {
    ull r; asm("mov.b64 %0, {%1, %2};" : "=l"(r) : "f"(lo), "f"(hi)); return r;
}
__device__ __forceinline__ void unpack2(ull v, float& lo, float& hi) {
    asm("mov.b64 {%0, %1}, %2;" : "=f"(lo), "=f"(hi) : "l"(v));
}
__device__ __forceinline__ ull fma2(ull a, ull b, ull c) {
    ull r; asm("fma.rn.f32x2 %0, %1, %2, %3;" : "=l"(r) : "l"(a), "l"(b), "l"(c)); return r;
}
__device__ __forceinline__ ull mul2(ull a, ull b) {
    ull r; asm("mul.rn.f32x2 %0, %1, %2;" : "=l"(r) : "l"(a), "l"(b)); return r;
}
// streaming (evict-first) 16B load as two packed f32 pairs
__device__ __forceinline__ void ldcs_v2u64(const void* p, ull& lo, ull& hi) {
    asm("ld.global.cs.v2.u64 {%0, %1}, [%2];" : "=l"(lo), "=l"(hi) : "l"(p));
}

#define LCL   (-13.28771237954945f)        /* lg2(1e-4) */
#define NEG_W (-0.34657359027997264f)      /* -0.5*ln(2) */

// acc += wgt2 * v^2 * max(lg2(1-v), LCL) for 4 elements (packed pairs)
// (validated in R7/R8 runs, rel_err 1.4e-7)
__device__ __forceinline__ void neg4_acc(ull w01, ull w23, ull wgt2,
                                         ull& acc0, ull& acc1,
                                         ull NEG1, ull ONE2) {
    ull q01 = fma2(w01, NEG1, ONE2);     // 1 - v (exact)
    ull q23 = fma2(w23, NEG1, ONE2);
    float q0, q1, q2, q3;
    unpack2(q01, q0, q1); unpack2(q23, q2, q3);
    float l0 = fmaxf(lg2f(q0), LCL), l1 = fmaxf(lg2f(q1), LCL);
    float l2 = fmaxf(lg2f(q2), LCL), l3 = fmaxf(lg2f(q3), LCL);
    ull L01 = pack2(l0, l1), L23 = pack2(l2, l3);
    ull t01 = mul2(w01, w01), t23 = mul2(w23, w23);
    acc0 = fma2(mul2(t01, L01), wgt2, acc0);
    acc1 = fma2(mul2(t23, L23), wgt2, acc1);
}

__global__ void __launch_bounds__(NTHR, 3)
focal_persistent_kernel(const float* __restrict__ cls,          // [B,A,C]
                        const float* __restrict__ regressions,  // [B,A,4]
                        const float* __restrict__ anchors,      // [A,4]
                        const float* __restrict__ annotations,  // [B,M,5]
                        float* __restrict__ out,
                        int A, int C, int M, int B,
                        int bx, int nTiles, int total_blocks)
{
    const int tid  = threadIdx.x;
    const int lane = tid & 31;
    const int warp = tid >> 5;

    __shared__ float4 s_box[MAX_M];
    __shared__ float  s_area[MAX_M];
    __shared__ float  s_lab[MAX_M];
    __shared__ float  s_w[ABLK];
    __shared__ float  sw_c[NWARP], sw_r[NWARP];
    __shared__ int    sw_i[NWARP];
    __shared__ int    s_t;
    __shared__ int    s_last;

    int curb = -1;    // image whose annotations are staged in smem

    // prime the queue
    if (tid == 0) s_t = atomicAdd(&g_tile_ctr, 1);
    __syncthreads();

    while (true) {
        const int t = s_t;               // everyone reads current tile
        __syncthreads();                 // all reads done before overwrite
        if (t >= nTiles) break;
        if (tid == 0) s_t = atomicAdd(&g_tile_ctr, 1);   // prefetch next
        const int b  = t >> 9;           // t / (A/ABLK) with A=65536: bx=512
        const int bb = (bx == 512) ? b : (t / bx);
        const int a0 = (t - bb * bx) * ABLK;
        const int nA = min(ABLK, A - a0);

        // ---- per-image annotation staging (changes every bx tiles) ----
        if (bb != curb) {
            if (tid < M) {
                const float* an = annotations + (size_t)bb * M * 5 + tid * 5;
                float x1 = an[0], y1 = an[1], x2 = an[2], y2 = an[3];
                s_box[tid]  = make_float4(x1, y1, x2, y2);
                s_area[tid] = (x2 - x1) * (y2 - y1);
                s_lab[tid]  = an[4];
            }
            curb = bb;
            __syncthreads();
        }

        // ================= Phase A: assignment (tid < nA active) ==========
        float fixsum = 0.0f, rsum = 0.0f;
        int   pcnt   = 0;

        if (tid < nA) {
            const int a = a0 + tid;
            float4 an = reinterpret_cast<const float4*>(anchors)[a];
            float aw = an.z - an.x;
            float ah = an.w - an.y;
            float area_a = aw * ah;

            float bin, bS;
            int   bi = 0;
            {
                float4 bo = s_box[0];
                float iw = fmaxf(fminf(an.z, bo.z) - fmaxf(an.x, bo.x), 0.0f);
                float ih = fmaxf(fminf(an.w, bo.w) - fmaxf(an.y, bo.y), 0.0f);
                bin = iw * ih;
                bS  = area_a + s_area[0];
            }
            #pragma unroll 8
            for (int m = 1; m < M; m++) {
                float4 bo = s_box[m];
                float iw = fmaxf(fminf(an.z, bo.z) - fmaxf(an.x, bo.x), 0.0f);
                float ih = fmaxf(fminf(an.w, bo.w) - fmaxf(an.y, bo.y), 0.0f);
                float inter = iw * ih;
                float S     = area_a + s_area[m];
                // iou_m > iou_best <=> inter*bS > bin*S (cross terms cancel)
                if (inter * bS > bin * S) { bi = m; bin = inter; bS = S; }
            }

            // iou >= 0.5 <=> 3*bin>=bS ; iou >= 0.4 <=> 3.5*bin>=bS
            bool pos = (3.0f * bin >= bS);
            bool ign = (!pos) && (3.5f * bin >= bS);
            s_w[tid] = ign ? 0.0f : NEG_W;

            if (pos) {
                pcnt++;
                float4 gb = s_box[bi];
                float gw = gb.z - gb.x, gh = gb.w - gb.y;
                float gcx = gb.x + 0.5f * gw, gcy = gb.y + 0.5f * gh;
                gw = fmaxf(gw, 1.0f);
                gh = fmaxf(gh, 1.0f);
                float acx = an.x + 0.5f * aw, acy = an.y + 0.5f * ah;
                float t0 = __fdividef(gcx - acx, aw) * 10.0f;
                float t1 = __fdividef(gcy - acy, ah) * 10.0f;
                float t2 = __logf(__fdividef(gw, aw)) * 5.0f;
                float t3 = __logf(__fdividef(gh, ah)) * 5.0f;

                float4 rg = reinterpret_cast<const float4*>(regressions)[(size_t)bb * A + a];
                const float th = 1.0f / 9.0f;
                const float c2 = 0.5f / 9.0f;
                float d;
                d = fabsf(t0 - rg.x); rsum += (d <= th) ? 4.5f * d * d : d - c2;
                d = fabsf(t1 - rg.y); rsum += (d <= th) ? 4.5f * d * d : d - c2;
                d = fabsf(t2 - rg.z); rsum += (d <= th) ? 4.5f * d * d : d - c2;
                d = fabsf(t3 - rg.w); rsum += (d <= th) ? 4.5f * d * d : d - c2;

                // classification fix-up: subtract the stream's neg term,
                // add the true positive term (same element math as neg4_acc)
                int label = (int)s_lab[bi];
                float v = cls[((size_t)bb * A + a) * C + label];
                fixsum -= NEG_W * (v * v * fmaxf(lg2f(1.0f - v), LCL));
                float pp = fminf(fmaxf(v, 1e-4f), 1.0f - 1e-4f);
                float qq = 1.0f - pp;
                fixsum += 0.5f * qq * qq * (-__logf(pp));
            }
        }
        __syncthreads();                 // s_w ready for phase B

        // ================= Phase B: classification stream =================
        float csum = fixsum;
        const ull NEG1 = pack2(-1.0f, -1.0f);
        const ull ONE2 = pack2(1.0f, 1.0f);

        if (C == 80 && nA == ABLK) {
            // 128 anchors * 20 float4 = 2560; 320 thr -> exactly 8 each,
            // ALL issued up front (MLP=8).
            const char* base = reinterpret_cast<const char*>(
                cls + ((size_t)bb * A + a0) * 80);
            ull p0a, p0b, p1a, p1b, p2a, p2b, p3a, p3b;
            ull p4a, p4b, p5a, p5b, p6a, p6b, p7a, p7b;
            const char* p = base + (size_t)tid * 16;
            ldcs_v2u64(p,                 p0a, p0b);
            ldcs_v2u64(p + 1 * NTHR * 16, p1a, p1b);
            ldcs_v2u64(p + 2 * NTHR * 16, p2a, p2b);
            ldcs_v2u64(p + 3 * NTHR * 16, p3a, p3b);
            ldcs_v2u64(p + 4 * NTHR * 16, p4a, p4b);
            ldcs_v2u64(p + 5 * NTHR * 16, p5a, p5b);
            ldcs_v2u64(p + 6 * NTHR * 16, p6a, p6b);
            ldcs_v2u64(p + 7 * NTHR * 16, p7a, p7b);

            const int la = tid / 20;     // anchor of load j is la + 16*j
            ull acc0 = pack2(0.0f, 0.0f), acc1 = pack2(0.0f, 0.0f);
            float w0 = s_w[la      ], w1 = s_w[la +  16];
            float w2 = s_w[la +  32], w3 = s_w[la +  48];
            float w4 = s_w[la +  64], w5 = s_w[la +  80];
            float w6 = s_w[la +  96], w7 = s_w[la + 112];
            neg4_acc(p0a, p0b, pack2(w0, w0), acc0, acc1, NEG1, ONE2);
            neg4_acc(p1a, p1b, pack2(w1, w1), acc0, acc1, NEG1, ONE2);
            neg4_acc(p2a, p2b, pack2(w2, w2), acc0, acc1, NEG1, ONE2);
            neg4_acc(p3a, p3b, pack2(w3, w3), acc0, acc1, NEG1, ONE2);
            neg4_acc(p4a, p4b, pack2(w4, w4), acc0, acc1, NEG1, ONE2);
            neg4_acc(p5a, p5b, pack2(w5, w5), acc0, acc1, NEG1, ONE2);
            neg4_acc(p6a, p6b, pack2(w6, w6), acc0, acc1, NEG1, ONE2);
            neg4_acc(p7a, p7b, pack2(w7, w7), acc0, acc1, NEG1, ONE2);
            float s0, s1, s2, s3;
            unpack2(acc0, s0, s1); unpack2(acc1, s2, s3);
            csum += (s0 + s1) + (s2 + s3);
        } else {
            // generic fallback (C % 4 == 0)
            const char* base = reinterpret_cast<const char*>(
                cls + ((size_t)bb * A + a0) * C);
            const int n4 = (nA * C) >> 2;
            ull acc0 = pack2(0.0f, 0.0f), acc1 = pack2(0.0f, 0.0f);
            for (int idx = tid; idx < n4; idx += NTHR) {
                int aa = (idx << 2) / C;
                float w = s_w[aa];
                ull va, vb;
                ldcs_v2u64(base + (size_t)idx * 16, va, vb);
                neg4_acc(va, vb, pack2(w, w), acc0, acc1, NEG1, ONE2);
            }
            float s0, s1, s2, s3;
            unpack2(acc0, s0, s1); unpack2(acc1, s2, s3);
            csum += (s0 + s1) + (s2 + s3);
        }

        // ---- per-tile block reduce + atomics ----
        float clssum = csum, regsum = rsum;
        int   poscnt = pcnt;
        #pragma unroll
        for (int off = 16; off > 0; off >>= 1) {
            clssum += __shfl_down_sync(0xFFFFFFFFu, clssum, off);
            regsum += __shfl_down_sync(0xFFFFFFFFu, regsum, off);
            poscnt += __shfl_down_sync(0xFFFFFFFFu, poscnt, off);
        }
        if (lane == 0) { sw_c[warp] = clssum; sw_r[warp] = regsum; sw_i[warp] = poscnt; }
        __syncthreads();
        if (warp == 0) {
            float cs = (lane < NWARP) ? sw_c[lane] : 0.0f;
            float rs = (lane < NWARP) ? sw_r[lane] : 0.0f;
            int   pc = (lane < NWARP) ? sw_i[lane] : 0;
            #pragma unroll
            for (int off = 8; off > 0; off >>= 1) {
                cs += __shfl_down_sync(0xFFFFFFFFu, cs, off);
                rs += __shfl_down_sync(0xFFFFFFFFu, rs, off);
                pc += __shfl_down_sync(0xFFFFFFFFu, pc, off);
            }
            if (lane == 0) {
                atomicAdd(&g_cls_sum[bb], (double)cs);
                if (rs != 0.0f) atomicAdd(&g_reg_sum[bb], (double)rs);
                if (pc != 0)    atomicAdd(&g_pos_cnt[bb], pc);
            }
        }
        __syncthreads();                 // reduce done; loop reads s_t next
    }

    // ================= ticket + finalize =================
    if (tid == 0) {
        __threadfence();
        int prev = atomicAdd(&g_done, 1);
        s_last = (prev == total_blocks - 1) ? 1 : 0;
    }
    __syncthreads();

    if (s_last) {
        __threadfence();
        if (warp == 0) {
            double cm = 0.0, rm = 0.0;
            if (lane < B) {
                double cv = *((volatile double*)&g_cls_sum[lane]);
                double rv = *((volatile double*)&g_reg_sum[lane]);
                int    pv = *((volatile int*)&g_pos_cnt[lane]);
                double np = (double)pv;
                cm = cv / fmax(np, 1.0);
                rm = (pv > 0) ? rv / fmax(np * 4.0, 1.0) : 0.0;
            }
            #pragma unroll
            for (int off = 16; off > 0; off >>= 1) {
                cm += __shfl_down_sync(0xFFFFFFFFu, cm, off);
                rm += __shfl_down_sync(0xFFFFFFFFu, rm, off);
            }
            if (lane == 0) {
                out[0] = (float)(cm / (double)B);
                out[1] = (float)(rm / (double)B);
                g_done = 0;
                g_tile_ctr = 0;
            }
            if (lane < B) {
                g_cls_sum[lane] = 0.0;
                g_reg_sum[lane] = 0.0;
                g_pos_cnt[lane] = 0;
            }
        }
    }
}

// ---------------------------------------------------------------------------
extern "C" void kernel_launch(void* const* d_in, const int* in_sizes, int n_in,
                              void* d_out, int out_size)
{
    const float* classifications = (const float*)d_in[0];  // [B,A,C]
    const float* regressions     = (const float*)d_in[1];  // [B,A,4]
    const float* anchors         = (const float*)d_in[2];  // [1,A,4]
    const float* annotations     = (const float*)d_in[3];  // [B,M,5]
    float* out = (float*)d_out;

    const int A = in_sizes[2] / 4;
    const int B = in_sizes[1] / (4 * A);
    const int C = in_sizes[0] / (B * A);
    const int M = in_sizes[3] / (5 * B);

    const int bx     = (A + ABLK - 1) / ABLK;   // 512 for A=65536
    const int nTiles = bx * B;                  // 4096

    focal_persistent_kernel<<<NBLK, NTHR>>>(classifications, regressions,
                                            anchors, annotations, out,
                                            A, C, M, B, bx, nTiles, NBLK);
    (void)n_in; (void)out_size;
}